// round 9
// baseline (speedup 1.0000x reference)
#include <cuda_runtime.h>

typedef unsigned long long ull;

__device__ __forceinline__ ull fma2(ull a, ull b, ull c){
    ull d; asm("fma.rn.f32x2 %0, %1, %2, %3;" : "=l"(d) : "l"(a), "l"(b), "l"(c)); return d;
}
__device__ __forceinline__ ull add2(ull a, ull b){
    ull d; asm("add.rn.f32x2 %0, %1, %2;" : "=l"(d) : "l"(a), "l"(b)); return d;
}
__device__ __forceinline__ ull mul2(ull a, ull b){
    ull d; asm("mul.rn.f32x2 %0, %1, %2;" : "=l"(d) : "l"(a), "l"(b)); return d;
}
__device__ __forceinline__ ull pack2(float x){
    ull d; asm("mov.b64 %0, {%1, %1};" : "=l"(d) : "f"(x)); return d;
}
__device__ __forceinline__ ull packf2(float x, float y){
    ull d; asm("mov.b64 %0, {%1, %2};" : "=l"(d) : "f"(x), "f"(y)); return d;
}
__device__ __forceinline__ void unpack2(ull v, float& x, float& y){
    asm("mov.b64 {%0, %1}, %2;" : "=f"(x), "=f"(y) : "l"(v));
}

// E=4, D=128, G=16, KF=16 (freqs=1..16), KTOP=2.
// Block = 160 threads (5 warps), batch = 32 rows, 4 CTAs/SM.
// DOUBLE-BUFFERED software pipeline, 2 barriers/batch:
//   barrier A -> stageB(i) into buf[p]  ||  stageA(i+1) into buf[1-p]
//   barrier B -> phase2(i) from buf[p]
// sFeat per row (stride 66 float2):
//   f2 [0..15]  : (sin_k, cos_k) pairs, k=1..16 (non-duplicated)
//   f2 [16..31] : spline (v,v)  [32..47] : gauss (v,v)  [48..63] : wavelet (v,v)
// Phase 2: warp = job (32 fma2/row, 8 LDS.128/row):
//   job0/1: fourier col-half (packed sin/cos, horizontal add, STG.64)
//   job2/3/4: spline/gauss/wavelet full 128 cols (STG.128)

#define FSTRIDE 66

__global__ __launch_bounds__(160, 4)
void mote_kernel(
    const float* __restrict__ timestamp,   // [B,1]
    const float* __restrict__ aux,         // [B,16]
    const float* __restrict__ router_W,    // [17,4]
    const float* __restrict__ router_b,    // [4]
    const float* __restrict__ freqs,       // [16]
    const float* __restrict__ fourier_W,   // [32,128]
    const float* __restrict__ knots,       // [16]
    const float* __restrict__ spline_W,    // [16,128]
    const float* __restrict__ centers,     // [16]
    const float* __restrict__ gauss_W,     // [16,128]
    const float* __restrict__ wav_centers, // [16]
    const float* __restrict__ wav_scales,  // [16]
    const float* __restrict__ wavelet_W,   // [16,128]
    float* __restrict__ out,
    int B)
{
    __shared__ __align__(16) float2 sFeat[2][32 * FSTRIDE];
    __shared__ float sDispP[2][4 * 32];
    __shared__ float sTime[2][32];

    const int tid  = threadIdx.x;
    const int wid  = tid >> 5;
    const int lane = tid & 31;

    // ---------------- phase-2 job setup (warp = job) ----------------
    const int job = wid;
    ull wA[16], wB[16];
    int cat = 0, foff = 0, dstA = 0;
    if (job < 2){
        const int cA = 64 * job + 2 * lane;
        #pragma unroll
        for (int k = 0; k < 16; k++){
            wA[k] = packf2(fourier_W[k*128 + cA],     fourier_W[(16+k)*128 + cA]);
            wB[k] = packf2(fourier_W[k*128 + cA + 1], fourier_W[(16+k)*128 + cA + 1]);
        }
        dstA = 32 * job + lane;
    } else {
        cat  = job - 1;                  // 1=spline, 2=gauss, 3=wavelet
        foff = 16 * cat;
        const float* Wexp = (cat == 1) ? spline_W : (cat == 2) ? gauss_W : wavelet_W;
        #pragma unroll
        for (int i = 0; i < 16; i++){
            wA[i] = ((const ull*)Wexp)[(size_t)i * 64 + 2*lane];
            wB[i] = ((const ull*)Wexp)[(size_t)i * 64 + 2*lane + 1];
        }
        dstA = cat * 64 + 2 * lane;
    }

    // ---------------- stage-B constants ----------------
    float bC = 0.f, bI = 0.f;
    if (wid == 2) bC = centers[lane & 15];
    else if (wid >= 3){ int j = lane & 15;
                        bC = wav_centers[j]; bI = __fdividef(1.f, wav_scales[j]); }

    // stage-A mapping: 4 threads per row, first 128 threads
    const int s4  = tid & 3;
    const int lr4 = tid >> 2;

    const size_t W_OFF = (size_t)B * 512;
    const size_t M_OFF = W_OFF + (size_t)B * 4;
    const int numBatches = B >> 5;       // 32 rows per batch
    const int stride = gridDim.x;
    const float E_M2 = 0.13533528324f;   // e^-2

    // prefetched stage-A inputs (for the next stageA call)
    float  tP = 0.f;
    float4 auxP = make_float4(0.f, 0.f, 0.f, 0.f);

    // stageA(b) consumes tP/auxP, writes sTime[pp]/sDispP[pp] + w/mask gmem,
    // then prefetches inputs for batch nb.
    auto stageA = [&](int b, int nb, int pp){
        if (tid >= 128) return;
        const int row = (b << 5) + lr4;
        const float t = tP;
        if (s4 == 0) sTime[pp][lr4] = t;

        const float4 xa = auxP;
        const float* Wq = router_W + (1 + 4 * s4) * 4;
        float p0 = xa.x*Wq[0] + xa.y*Wq[4] + xa.z*Wq[8]  + xa.w*Wq[12];
        float p1 = xa.x*Wq[1] + xa.y*Wq[5] + xa.z*Wq[9]  + xa.w*Wq[13];
        float p2 = xa.x*Wq[2] + xa.y*Wq[6] + xa.z*Wq[10] + xa.w*Wq[14];
        float p3 = xa.x*Wq[3] + xa.y*Wq[7] + xa.z*Wq[11] + xa.w*Wq[15];
        if (s4 == 0){
            p0 += t*router_W[0] + router_b[0];
            p1 += t*router_W[1] + router_b[1];
            p2 += t*router_W[2] + router_b[2];
            p3 += t*router_W[3] + router_b[3];
        }
        p0 += __shfl_xor_sync(0xffffffffu, p0, 1);
        p1 += __shfl_xor_sync(0xffffffffu, p1, 1);
        p2 += __shfl_xor_sync(0xffffffffu, p2, 1);
        p3 += __shfl_xor_sync(0xffffffffu, p3, 1);
        p0 += __shfl_xor_sync(0xffffffffu, p0, 2);
        p1 += __shfl_xor_sync(0xffffffffu, p1, 2);
        p2 += __shfl_xor_sync(0xffffffffu, p2, 2);
        p3 += __shfl_xor_sync(0xffffffffu, p3, 2);

        float m  = fmaxf(fmaxf(p0, p1), fmaxf(p2, p3));
        float e0 = __expf(p0 - m), e1 = __expf(p1 - m);
        float e2 = __expf(p2 - m), e3 = __expf(p3 - m);
        float inv = __fdividef(1.0f, e0 + e1 + e2 + e3);
        float w0 = e0*inv, w1 = e1*inv, w2 = e2*inv, w3 = e3*inv;

        int r0 = (w1 >  w0) + (w2 >  w0) + (w3 >  w0);
        int r1 = (w0 >= w1) + (w2 >  w1) + (w3 >  w1);
        int r2 = (w0 >= w2) + (w1 >= w2) + (w3 >  w2);
        int r3 = (w0 >= w3) + (w1 >= w3) + (w2 >= w3);

        float ws = (s4==0) ? w0 : (s4==1) ? w1 : (s4==2) ? w2 : w3;
        int   rs = (s4==0) ? r0 : (s4==1) ? r1 : (s4==2) ? r2 : r3;
        sDispP[pp][s4*32 + lr4] = (rs < 2) ? ws : 0.f;
        out[W_OFF + (size_t)row*4 + s4] = ws;
        out[M_OFF + (size_t)row*4 + s4] = (rs < 2) ? 1.0f : 0.0f;

        if (nb < numBatches){
            const int nrow = (nb << 5) + lr4;
            tP   = timestamp[nrow];
            auxP = ((const float4*)(aux + (size_t)nrow * 16))[s4];
        }
    };

    // ---------------- prologue: stage A for first batch ----------------
    const int b0 = blockIdx.x;
    if (tid < 128 && b0 < numBatches){
        const int row = (b0 << 5) + lr4;
        tP   = timestamp[row];
        auxP = ((const float4*)(aux + (size_t)row * 16))[s4];
    }
    if (b0 < numBatches) stageA(b0, b0 + stride, 0);

    int p = 0;
    for (int batch = b0; batch < numBatches; batch += stride){
        __syncthreads();   // barrier A: sTime[p]/sDispP[p] ready, sFeat[p] free

        // ===== stage B: raw features for batch -> sFeat[p] =====
        if (wid == 0){
            const float t = sTime[p][lane];
            float4* dst = (float4*)(sFeat[p] + lane * FSTRIDE);
            float s1 = __sinf(t), c1 = __cosf(t);
            float sk = s1, ck = c1;
            #pragma unroll
            for (int m2 = 0; m2 < 8; m2++){
                float sa = sk, ca = ck;
                float sb = fmaf(sa, c1,  ca * s1);
                float cb = fmaf(ca, c1, -sa * s1);
                dst[m2] = make_float4(sa, ca, sb, cb);
                sk = fmaf(sb, c1,  cb * s1);
                ck = fmaf(cb, c1, -sb * s1);
            }
        } else if (wid == 1){
            const float t = sTime[p][lane];
            float2* dst = sFeat[p] + lane * FSTRIDE + 16;
            const float a = (t + 2.0f) * 3.75f;
            int j0 = __float2int_rn(a);
            j0 = max(0, min(15, j0));
            const float d = a - (float)j0;
            const float f0 = __expf(-d * d);
            dst[j0] = make_float2(f0, f0);
            float f = f0, r = __expf(fmaf(2.0f, d, -1.0f));
            #pragma unroll
            for (int k = 1; k <= 15; k++){
                f *= r; r *= E_M2;
                if (j0 + k <= 15) dst[j0 + k] = make_float2(f, f);
            }
            f = f0; r = __expf(fmaf(-2.0f, d, -1.0f));
            #pragma unroll
            for (int k = 1; k <= 15; k++){
                f *= r; r *= E_M2;
                if (j0 - k >= 0) dst[j0 - k] = make_float2(f, f);
            }
        } else if (wid == 2){
            const int j  = lane & 15;
            const int r0 = (lane >> 4) << 4;
            #pragma unroll 4
            for (int k = 0; k < 16; k++){
                const int row = r0 + k;
                const float u = sTime[p][row] - bC;
                const float v = __expf(-u * u);
                sFeat[p][row * FSTRIDE + 32 + j] = make_float2(v, v);
            }
        } else {
            const int j  = lane & 15;
            const int r0 = (((wid - 3) << 1) + (lane >> 4)) << 3;
            #pragma unroll 4
            for (int k = 0; k < 8; k++){
                const int row = r0 + k;
                const float u  = (sTime[p][row] - bC) * bI;
                const float uu = u * u;
                const float v  = (1.0f - uu) * __expf(-0.5f * uu);
                sFeat[p][row * FSTRIDE + 48 + j] = make_float2(v, v);
            }
        }

        // ===== stage A for NEXT batch -> buf[1-p] (off critical path) =====
        const int nb = batch + stride;
        if (nb < numBatches) stageA(nb, nb + stride, p ^ 1);

        __syncthreads();   // barrier B: sFeat[p] ready

        // ===== phase 2: matvecs for current batch =====
        const float selv = sDispP[p][cat*32 + lane];
        const unsigned act = __ballot_sync(0xffffffffu, selv != 0.f);
        ull* obase = (ull*)out + ((size_t)batch << 5) * 256 + dstA;
        const float2* fbase = sFeat[p];

        if (job < 2){
            #pragma unroll 4
            for (int r = 0; r < 32; r++){
                ull* o = obase + (size_t)r * 256;
                const float s = __shfl_sync(0xffffffffu, selv, r);
                if (act & (1u << r)){
                    const float2* feat = fbase + r * FSTRIDE;
                    ull a0 = 0, a1 = 0, a2 = 0, a3 = 0;
                    #pragma unroll
                    for (int i = 0; i < 8; i++){
                        ulonglong2 F = *(const ulonglong2*)(feat + 2*i);
                        a0 = fma2(wA[2*i],   F.x, a0);
                        a1 = fma2(wA[2*i+1], F.y, a1);
                        a2 = fma2(wB[2*i],   F.x, a2);
                        a3 = fma2(wB[2*i+1], F.y, a3);
                    }
                    float lA, hA, lB, hB;
                    unpack2(add2(a0, a1), lA, hA);
                    unpack2(add2(a2, a3), lB, hB);
                    *o = packf2((lA + hA) * s, (lB + hB) * s);
                } else *o = 0ull;
            }
        } else {
            #pragma unroll 4
            for (int r = 0; r < 32; r++){
                ulonglong2* o = (ulonglong2*)(obase + (size_t)r * 256);
                const float s = __shfl_sync(0xffffffffu, selv, r);
                ulonglong2 res;
                if (act & (1u << r)){
                    const float2* feat = fbase + r * FSTRIDE + foff;
                    ull a0 = 0, a1 = 0, a2 = 0, a3 = 0;
                    #pragma unroll
                    for (int i = 0; i < 8; i++){
                        ulonglong2 F = *(const ulonglong2*)(feat + 2*i);
                        a0 = fma2(wA[2*i],   F.x, a0);
                        a1 = fma2(wA[2*i+1], F.y, a1);
                        a2 = fma2(wB[2*i],   F.x, a2);
                        a3 = fma2(wB[2*i+1], F.y, a3);
                    }
                    const ull sv = pack2(s);
                    res.x = mul2(add2(a0, a1), sv);
                    res.y = mul2(add2(a2, a3), sv);
                } else { res.x = 0ull; res.y = 0ull; }
                *o = res;
            }
        }

        p ^= 1;
    }
}

extern "C" void kernel_launch(void* const* d_in, const int* in_sizes, int n_in,
                              void* d_out, int out_size)
{
    const float* timestamp   = (const float*)d_in[0];
    const float* aux         = (const float*)d_in[1];
    const float* router_W    = (const float*)d_in[2];
    const float* router_b    = (const float*)d_in[3];
    const float* freqs       = (const float*)d_in[4];
    const float* fourier_W   = (const float*)d_in[5];
    const float* knots       = (const float*)d_in[6];
    const float* spline_W    = (const float*)d_in[7];
    const float* centers     = (const float*)d_in[8];
    const float* gauss_W     = (const float*)d_in[9];
    const float* wav_centers = (const float*)d_in[10];
    const float* wav_scales  = (const float*)d_in[11];
    const float* wavelet_W   = (const float*)d_in[12];
    float* out = (float*)d_out;

    const int B = in_sizes[0];

    mote_kernel<<<592, 160>>>(timestamp, aux, router_W, router_b, freqs,
                              fourier_W, knots, spline_W, centers, gauss_W,
                              wav_centers, wav_scales, wavelet_W, out, B);
}

// round 12
// speedup vs baseline: 1.0812x; 1.0812x over previous
#include <cuda_runtime.h>

typedef unsigned long long ull;

__device__ __forceinline__ ull fma2(ull a, ull b, ull c){
    ull d; asm("fma.rn.f32x2 %0, %1, %2, %3;" : "=l"(d) : "l"(a), "l"(b), "l"(c)); return d;
}
__device__ __forceinline__ ull add2(ull a, ull b){
    ull d; asm("add.rn.f32x2 %0, %1, %2;" : "=l"(d) : "l"(a), "l"(b)); return d;
}
__device__ __forceinline__ ull mul2(ull a, ull b){
    ull d; asm("mul.rn.f32x2 %0, %1, %2;" : "=l"(d) : "l"(a), "l"(b)); return d;
}
__device__ __forceinline__ ull pack2(float x){
    ull d; asm("mov.b64 %0, {%1, %1};" : "=l"(d) : "f"(x)); return d;
}
__device__ __forceinline__ ull packf2(float x, float y){
    ull d; asm("mov.b64 %0, {%1, %2};" : "=l"(d) : "f"(x), "f"(y)); return d;
}
__device__ __forceinline__ void unpack2(ull v, float& x, float& y){
    asm("mov.b64 {%0, %1}, %2;" : "=f"(x), "=f"(y) : "l"(v));
}

// E=4, D=128, G=16, KF=16 (freqs=1..16), KTOP=2.
// Block = 320 threads (10 warps), batch = 64 rows, 2 CTAs/SM. (proven R6 shape)
// 2 barriers/batch: stageA(i)[parity p] -> sync -> stageB(i) -> sync -> phase2(i).
// sDispP/sTime double-buffered so stageA needs no leading barrier.
// sFeat per row (stride 66 float2):
//   f2 [0..15]  : (sin_k, cos_k) pairs, k=1..16 (non-duplicated)
//   f2 [16..31] : spline (v,v)  [32..47] : gauss (v,v)  [48..63] : wavelet (v,v)
// Phase 2: 10 warps = 2 row-streams x 5 jobs (32 fma2/row, 8 LDS.128/row):
//   job0/1: fourier col-half (packed sin/cos, horizontal add, STG.64)
//   job2/3/4: spline/gauss/wavelet full 128 cols (STG.128)

#define FSTRIDE 66

__global__ __launch_bounds__(320, 2)
void mote_kernel(
    const float* __restrict__ timestamp,   // [B,1]
    const float* __restrict__ aux,         // [B,16]
    const float* __restrict__ router_W,    // [17,4]
    const float* __restrict__ router_b,    // [4]
    const float* __restrict__ freqs,       // [16]
    const float* __restrict__ fourier_W,   // [32,128]
    const float* __restrict__ knots,       // [16]
    const float* __restrict__ spline_W,    // [16,128]
    const float* __restrict__ centers,     // [16]
    const float* __restrict__ gauss_W,     // [16,128]
    const float* __restrict__ wav_centers, // [16]
    const float* __restrict__ wav_scales,  // [16]
    const float* __restrict__ wavelet_W,   // [16,128]
    float* __restrict__ out,
    int B)
{
    __shared__ __align__(16) float2 sFeat[64 * FSTRIDE];
    __shared__ float sDispP[2][4 * 64];
    __shared__ float sTime[2][64];

    const int tid  = threadIdx.x;
    const int wid  = tid >> 5;
    const int lane = tid & 31;

    // ---------------- phase-2 job setup (per warp) ----------------
    const int job  = wid % 5;
    const int strm = wid / 5;
    ull wA[16], wB[16];
    int cat = 0, foff = 0, dstA = 0;
    if (job < 2){
        const int cA = 64 * job + 2 * lane;
        #pragma unroll
        for (int k = 0; k < 16; k++){
            wA[k] = packf2(fourier_W[k*128 + cA],     fourier_W[(16+k)*128 + cA]);
            wB[k] = packf2(fourier_W[k*128 + cA + 1], fourier_W[(16+k)*128 + cA + 1]);
        }
        dstA = 32 * job + lane;
    } else {
        cat  = job - 1;                  // 1=spline, 2=gauss, 3=wavelet
        foff = 16 * cat;
        const float* Wexp = (cat == 1) ? spline_W : (cat == 2) ? gauss_W : wavelet_W;
        #pragma unroll
        for (int i = 0; i < 16; i++){
            wA[i] = ((const ull*)Wexp)[(size_t)i * 64 + 2*lane];
            wB[i] = ((const ull*)Wexp)[(size_t)i * 64 + 2*lane + 1];
        }
        dstA = cat * 64 + 2 * lane;
    }

    // ---------------- stage-B constants ----------------
    float bC = 0.f, bI = 0.f;
    if (wid == 4 || wid == 5)      bC = centers[(tid - 128) & 15];
    else if (wid >= 6){ int j = (tid - 192) & 15;
                        bC = wav_centers[j]; bI = __fdividef(1.f, wav_scales[j]); }

    // stage-A mapping: 4 threads per row, first 256 threads
    const int s4  = tid & 3;
    const int lr4 = tid >> 2;

    const size_t W_OFF = (size_t)B * 512;
    const size_t M_OFF = W_OFF + (size_t)B * 4;
    const int numBatches = B >> 6;       // 64 rows per batch
    const int stride = gridDim.x;
    const float E_M2 = 0.13533528324f;   // e^-2

    // ---------------- prefetch first batch's stage-A inputs ----------------
    float  tP = 0.f;
    float4 auxP = make_float4(0.f, 0.f, 0.f, 0.f);
    if (tid < 256 && blockIdx.x < numBatches){
        const int row = (blockIdx.x << 6) + lr4;
        tP   = timestamp[row];
        auxP = ((const float4*)(aux + (size_t)row * 16))[s4];
    }

    int p = 0;
    for (int batch = blockIdx.x; batch < numBatches; batch += stride){
        const int rowBase = batch << 6;

        // ===== stage A (parity p): router + w/mask; no leading barrier ======
        if (tid < 256){
            const int row = rowBase + lr4;
            const float t = tP;
            if (s4 == 0) sTime[p][lr4] = t;

            const float4 xa = auxP;
            const float* Wq = router_W + (1 + 4 * s4) * 4;
            float p0 = xa.x*Wq[0] + xa.y*Wq[4] + xa.z*Wq[8]  + xa.w*Wq[12];
            float p1 = xa.x*Wq[1] + xa.y*Wq[5] + xa.z*Wq[9]  + xa.w*Wq[13];
            float p2 = xa.x*Wq[2] + xa.y*Wq[6] + xa.z*Wq[10] + xa.w*Wq[14];
            float p3 = xa.x*Wq[3] + xa.y*Wq[7] + xa.z*Wq[11] + xa.w*Wq[15];
            if (s4 == 0){
                p0 += t*router_W[0] + router_b[0];
                p1 += t*router_W[1] + router_b[1];
                p2 += t*router_W[2] + router_b[2];
                p3 += t*router_W[3] + router_b[3];
            }
            p0 += __shfl_xor_sync(0xffffffffu, p0, 1);
            p1 += __shfl_xor_sync(0xffffffffu, p1, 1);
            p2 += __shfl_xor_sync(0xffffffffu, p2, 1);
            p3 += __shfl_xor_sync(0xffffffffu, p3, 1);
            p0 += __shfl_xor_sync(0xffffffffu, p0, 2);
            p1 += __shfl_xor_sync(0xffffffffu, p1, 2);
            p2 += __shfl_xor_sync(0xffffffffu, p2, 2);
            p3 += __shfl_xor_sync(0xffffffffu, p3, 2);

            float m  = fmaxf(fmaxf(p0, p1), fmaxf(p2, p3));
            float e0 = __expf(p0 - m), e1 = __expf(p1 - m);
            float e2 = __expf(p2 - m), e3 = __expf(p3 - m);
            float inv = __fdividef(1.0f, e0 + e1 + e2 + e3);
            float w0 = e0*inv, w1 = e1*inv, w2 = e2*inv, w3 = e3*inv;

            int r0 = (w1 >  w0) + (w2 >  w0) + (w3 >  w0);
            int r1 = (w0 >= w1) + (w2 >  w1) + (w3 >  w1);
            int r2 = (w0 >= w2) + (w1 >= w2) + (w3 >  w2);
            int r3 = (w0 >= w3) + (w1 >= w3) + (w2 >= w3);

            float ws = (s4==0) ? w0 : (s4==1) ? w1 : (s4==2) ? w2 : w3;
            int   rs = (s4==0) ? r0 : (s4==1) ? r1 : (s4==2) ? r2 : r3;
            sDispP[p][s4*64 + lr4] = (rs < 2) ? ws : 0.f;
            out[W_OFF + (size_t)row*4 + s4] = ws;
            out[M_OFF + (size_t)row*4 + s4] = (rs < 2) ? 1.0f : 0.0f;

            // prefetch next batch's inputs; lands during stage B / phase 2
            const int nb = batch + stride;
            if (nb < numBatches){
                const int nrow = (nb << 6) + lr4;
                tP   = timestamp[nrow];
                auxP = ((const float4*)(aux + (size_t)nrow * 16))[s4];
            }
        }
        __syncthreads();   // phase2(prev) done with sFeat; sTime/sDispP[p] visible

        // ================= stage B: raw features, warp-specialized ==========
        if (wid < 2){
            const int row = tid;
            const float t = sTime[p][row];
            float4* dst = (float4*)(sFeat + row * FSTRIDE);
            float s1 = __sinf(t), c1 = __cosf(t);
            float sk = s1, ck = c1;
            #pragma unroll
            for (int m2 = 0; m2 < 8; m2++){
                float sa = sk, ca = ck;
                float sb = fmaf(sa, c1,  ca * s1);
                float cb = fmaf(ca, c1, -sa * s1);
                dst[m2] = make_float4(sa, ca, sb, cb);
                sk = fmaf(sb, c1,  cb * s1);
                ck = fmaf(cb, c1, -sb * s1);
            }
        } else if (wid < 4){
            const int row = tid - 64;
            const float t = sTime[p][row];
            float2* dst = sFeat + row * FSTRIDE + 16;
            const float a = (t + 2.0f) * 3.75f;
            int j0 = __float2int_rn(a);
            j0 = max(0, min(15, j0));
            const float d = a - (float)j0;
            const float f0 = __expf(-d * d);
            dst[j0] = make_float2(f0, f0);
            float f = f0, r = __expf(fmaf(2.0f, d, -1.0f));
            #pragma unroll
            for (int k = 1; k <= 15; k++){
                f *= r; r *= E_M2;
                if (j0 + k <= 15) dst[j0 + k] = make_float2(f, f);
            }
            f = f0; r = __expf(fmaf(-2.0f, d, -1.0f));
            #pragma unroll
            for (int k = 1; k <= 15; k++){
                f *= r; r *= E_M2;
                if (j0 - k >= 0) dst[j0 - k] = make_float2(f, f);
            }
        } else if (wid < 6){
            const int tt = tid - 128;
            const int j  = tt & 15;
            const int r0 = (tt >> 4) << 4;
            #pragma unroll 4
            for (int k = 0; k < 16; k++){
                const int row = r0 + k;
                const float u = sTime[p][row] - bC;
                const float v = __expf(-u * u);
                sFeat[row * FSTRIDE + 32 + j] = make_float2(v, v);
            }
        } else {
            const int tt = tid - 192;
            const int j  = tt & 15;
            const int r0 = (tt >> 4) << 3;
            #pragma unroll 4
            for (int k = 0; k < 8; k++){
                const int row = r0 + k;
                const float u  = (sTime[p][row] - bC) * bI;
                const float uu = u * u;
                const float v  = (1.0f - uu) * __expf(-0.5f * uu);
                sFeat[row * FSTRIDE + 48 + j] = make_float2(v, v);
            }
        }
        __syncthreads();   // sFeat ready

        // ================= phase 2: matvecs (warp = job, 32 rows/stream) ====
        const int rb = strm * 32;
        const float selv = sDispP[p][cat*64 + rb + lane];
        const unsigned act = __ballot_sync(0xffffffffu, selv != 0.f);
        ull* obase = (ull*)out + (size_t)(rowBase + rb) * 256 + dstA;

        if (job < 2){
            #pragma unroll 4
            for (int r = 0; r < 32; r++){
                ull* o = obase + (size_t)r * 256;
                const float s = __shfl_sync(0xffffffffu, selv, r);
                if (act & (1u << r)){
                    const float2* feat = sFeat + (rb + r) * FSTRIDE;
                    ull a0 = 0, a1 = 0, a2 = 0, a3 = 0;
                    #pragma unroll
                    for (int i = 0; i < 8; i++){
                        ulonglong2 F = *(const ulonglong2*)(feat + 2*i);
                        a0 = fma2(wA[2*i],   F.x, a0);
                        a1 = fma2(wA[2*i+1], F.y, a1);
                        a2 = fma2(wB[2*i],   F.x, a2);
                        a3 = fma2(wB[2*i+1], F.y, a3);
                    }
                    float lA, hA, lB, hB;
                    unpack2(add2(a0, a1), lA, hA);
                    unpack2(add2(a2, a3), lB, hB);
                    *o = packf2((lA + hA) * s, (lB + hB) * s);
                } else *o = 0ull;
            }
        } else {
            #pragma unroll 4
            for (int r = 0; r < 32; r++){
                ulonglong2* o = (ulonglong2*)(obase + (size_t)r * 256);
                const float s = __shfl_sync(0xffffffffu, selv, r);
                ulonglong2 res;
                if (act & (1u << r)){
                    const float2* feat = sFeat + (rb + r) * FSTRIDE + foff;
                    ull a0 = 0, a1 = 0, a2 = 0, a3 = 0;
                    #pragma unroll
                    for (int i = 0; i < 8; i++){
                        ulonglong2 F = *(const ulonglong2*)(feat + 2*i);
                        a0 = fma2(wA[2*i],   F.x, a0);
                        a1 = fma2(wA[2*i+1], F.y, a1);
                        a2 = fma2(wB[2*i],   F.x, a2);
                        a3 = fma2(wB[2*i+1], F.y, a3);
                    }
                    const ull sv = pack2(s);
                    res.x = mul2(add2(a0, a1), sv);
                    res.y = mul2(add2(a2, a3), sv);
                } else { res.x = 0ull; res.y = 0ull; }
                *o = res;
            }
        }

        p ^= 1;
    }
}

extern "C" void kernel_launch(void* const* d_in, const int* in_sizes, int n_in,
                              void* d_out, int out_size)
{
    const float* timestamp   = (const float*)d_in[0];
    const float* aux         = (const float*)d_in[1];
    const float* router_W    = (const float*)d_in[2];
    const float* router_b    = (const float*)d_in[3];
    const float* freqs       = (const float*)d_in[4];
    const float* fourier_W   = (const float*)d_in[5];
    const float* knots       = (const float*)d_in[6];
    const float* spline_W    = (const float*)d_in[7];
    const float* centers     = (const float*)d_in[8];
    const float* gauss_W     = (const float*)d_in[9];
    const float* wav_centers = (const float*)d_in[10];
    const float* wav_scales  = (const float*)d_in[11];
    const float* wavelet_W   = (const float*)d_in[12];
    float* out = (float*)d_out;

    const int B = in_sizes[0];

    mote_kernel<<<296, 320>>>(timestamp, aux, router_W, router_b, freqs,
                              fourier_W, knots, spline_W, centers, gauss_W,
                              wav_centers, wav_scales, wavelet_W, out, B);
}

// round 17
// speedup vs baseline: 1.2044x; 1.1139x over previous
#include <cuda_runtime.h>

typedef unsigned long long ull;

__device__ __forceinline__ ull fma2(ull a, ull b, ull c){
    ull d; asm("fma.rn.f32x2 %0, %1, %2, %3;" : "=l"(d) : "l"(a), "l"(b), "l"(c)); return d;
}
__device__ __forceinline__ ull add2(ull a, ull b){
    ull d; asm("add.rn.f32x2 %0, %1, %2;" : "=l"(d) : "l"(a), "l"(b)); return d;
}
__device__ __forceinline__ ull packf2(float x, float y){
    ull d; asm("mov.b64 %0, {%1, %2};" : "=l"(d) : "f"(x), "f"(y)); return d;
}
__device__ __forceinline__ void unpack2(ull v, float& x, float& y){
    asm("mov.b64 {%0, %1}, %2;" : "=f"(x), "=f"(y) : "l"(v));
}

// E=4, D=128, G=16, KF=16 (freqs=1..16), KTOP=2.
// Block = 320 threads (10 warps), batch = 64 rows, 2 CTAs/SM (proven shape).
// 2 barriers/batch; sDispP/sTime double-buffered (stage A needs no lead barrier).
// Stage B PRE-SCALES all features by the dispatch weight of their category, so
// phase 2 has NO per-row sel broadcast / multiply — just fma chain + store.
// sFeat per row (stride 66 float2):
//   f2 [0..15]  : (sin_k*d0, cos_k*d0) pairs, k=1..16
//   f2 [16..31] : spline*d1 (v,v)  [32..47] : gauss*d2 (v,v)  [48..63] : wavelet*d3 (v,v)
// Phase 2: 10 warps = 2 row-streams x 5 jobs (32 fma2/row, 8 LDS.128/row):
//   job0/1: fourier col-half (packed sin/cos, horizontal add, STG.64)
//   job2/3/4: spline/gauss/wavelet full 128 cols (STG.128)

#define FSTRIDE 66

__global__ __launch_bounds__(320, 2)
void mote_kernel(
    const float* __restrict__ timestamp,   // [B,1]
    const float* __restrict__ aux,         // [B,16]
    const float* __restrict__ router_W,    // [17,4]
    const float* __restrict__ router_b,    // [4]
    const float* __restrict__ freqs,       // [16]
    const float* __restrict__ fourier_W,   // [32,128]
    const float* __restrict__ knots,       // [16]
    const float* __restrict__ spline_W,    // [16,128]
    const float* __restrict__ centers,     // [16]
    const float* __restrict__ gauss_W,     // [16,128]
    const float* __restrict__ wav_centers, // [16]
    const float* __restrict__ wav_scales,  // [16]
    const float* __restrict__ wavelet_W,   // [16,128]
    float* __restrict__ out,
    int B)
{
    __shared__ __align__(16) float2 sFeat[64 * FSTRIDE];
    __shared__ float sDispP[2][4 * 64];
    __shared__ float sTime[2][64];

    const int tid  = threadIdx.x;
    const int wid  = tid >> 5;
    const int lane = tid & 31;

    // ---------------- phase-2 job setup (per warp) ----------------
    const int job  = wid % 5;
    const int strm = wid / 5;
    ull wA[16], wB[16];
    int cat = 0, foff = 0, dstA = 0;
    if (job < 2){
        const int cA = 64 * job + 2 * lane;
        #pragma unroll
        for (int k = 0; k < 16; k++){
            wA[k] = packf2(fourier_W[k*128 + cA],     fourier_W[(16+k)*128 + cA]);
            wB[k] = packf2(fourier_W[k*128 + cA + 1], fourier_W[(16+k)*128 + cA + 1]);
        }
        dstA = 32 * job + lane;
    } else {
        cat  = job - 1;                  // 1=spline, 2=gauss, 3=wavelet
        foff = 16 * cat;
        const float* Wexp = (cat == 1) ? spline_W : (cat == 2) ? gauss_W : wavelet_W;
        #pragma unroll
        for (int i = 0; i < 16; i++){
            wA[i] = ((const ull*)Wexp)[(size_t)i * 64 + 2*lane];
            wB[i] = ((const ull*)Wexp)[(size_t)i * 64 + 2*lane + 1];
        }
        dstA = cat * 64 + 2 * lane;
    }

    // ---------------- stage-B constants ----------------
    float bC = 0.f, bI = 0.f;
    if (wid == 4 || wid == 5)      bC = centers[(tid - 128) & 15];
    else if (wid >= 6){ int j = (tid - 192) & 15;
                        bC = wav_centers[j]; bI = __fdividef(1.f, wav_scales[j]); }

    // stage-A mapping: 4 threads per row, first 256 threads
    const int s4  = tid & 3;
    const int lr4 = tid >> 2;

    const size_t W_OFF = (size_t)B * 512;
    const size_t M_OFF = W_OFF + (size_t)B * 4;
    const int numBatches = B >> 6;       // 64 rows per batch
    const int stride = gridDim.x;
    const float E_M2 = 0.13533528324f;   // e^-2

    // ---------------- prefetch first batch's stage-A inputs ----------------
    float  tP = 0.f;
    float4 auxP = make_float4(0.f, 0.f, 0.f, 0.f);
    if (tid < 256 && blockIdx.x < numBatches){
        const int row = (blockIdx.x << 6) + lr4;
        tP   = timestamp[row];
        auxP = ((const float4*)(aux + (size_t)row * 16))[s4];
    }

    int p = 0;
    for (int batch = blockIdx.x; batch < numBatches; batch += stride){
        const int rowBase = batch << 6;

        // ===== stage A (parity p): router + w/mask; no leading barrier ======
        if (tid < 256){
            const int row = rowBase + lr4;
            const float t = tP;
            if (s4 == 0) sTime[p][lr4] = t;

            const float4 xa = auxP;
            const float* Wq = router_W + (1 + 4 * s4) * 4;
            float p0 = xa.x*Wq[0] + xa.y*Wq[4] + xa.z*Wq[8]  + xa.w*Wq[12];
            float p1 = xa.x*Wq[1] + xa.y*Wq[5] + xa.z*Wq[9]  + xa.w*Wq[13];
            float p2 = xa.x*Wq[2] + xa.y*Wq[6] + xa.z*Wq[10] + xa.w*Wq[14];
            float p3 = xa.x*Wq[3] + xa.y*Wq[7] + xa.z*Wq[11] + xa.w*Wq[15];
            if (s4 == 0){
                p0 += t*router_W[0] + router_b[0];
                p1 += t*router_W[1] + router_b[1];
                p2 += t*router_W[2] + router_b[2];
                p3 += t*router_W[3] + router_b[3];
            }
            p0 += __shfl_xor_sync(0xffffffffu, p0, 1);
            p1 += __shfl_xor_sync(0xffffffffu, p1, 1);
            p2 += __shfl_xor_sync(0xffffffffu, p2, 1);
            p3 += __shfl_xor_sync(0xffffffffu, p3, 1);
            p0 += __shfl_xor_sync(0xffffffffu, p0, 2);
            p1 += __shfl_xor_sync(0xffffffffu, p1, 2);
            p2 += __shfl_xor_sync(0xffffffffu, p2, 2);
            p3 += __shfl_xor_sync(0xffffffffu, p3, 2);

            float m  = fmaxf(fmaxf(p0, p1), fmaxf(p2, p3));
            float e0 = __expf(p0 - m), e1 = __expf(p1 - m);
            float e2 = __expf(p2 - m), e3 = __expf(p3 - m);
            float inv = __fdividef(1.0f, e0 + e1 + e2 + e3);
            float w0 = e0*inv, w1 = e1*inv, w2 = e2*inv, w3 = e3*inv;

            int r0 = (w1 >  w0) + (w2 >  w0) + (w3 >  w0);
            int r1 = (w0 >= w1) + (w2 >  w1) + (w3 >  w1);
            int r2 = (w0 >= w2) + (w1 >= w2) + (w3 >  w2);
            int r3 = (w0 >= w3) + (w1 >= w3) + (w2 >= w3);

            float ws = (s4==0) ? w0 : (s4==1) ? w1 : (s4==2) ? w2 : w3;
            int   rs = (s4==0) ? r0 : (s4==1) ? r1 : (s4==2) ? r2 : r3;
            sDispP[p][s4*64 + lr4] = (rs < 2) ? ws : 0.f;
            out[W_OFF + (size_t)row*4 + s4] = ws;
            out[M_OFF + (size_t)row*4 + s4] = (rs < 2) ? 1.0f : 0.0f;

            // prefetch next batch's inputs; lands during stage B / phase 2
            const int nb = batch + stride;
            if (nb < numBatches){
                const int nrow = (nb << 6) + lr4;
                tP   = timestamp[nrow];
                auxP = ((const float4*)(aux + (size_t)nrow * 16))[s4];
            }
        }
        __syncthreads();   // phase2(prev) done with sFeat; sTime/sDispP[p] visible

        // ======= stage B: features PRE-SCALED by dispatch, warp-specialized =
        if (wid < 2){
            // trig: thread = row; sin/cos ladder (2 MUFU); scale at store by d0
            const int row = tid;
            const float t  = sTime[p][row];
            const float d0 = sDispP[p][row];              // fourier dispatch
            float4* dst = (float4*)(sFeat + row * FSTRIDE);
            float s1 = __sinf(t), c1 = __cosf(t);
            float sk = s1, ck = c1;
            #pragma unroll
            for (int m2 = 0; m2 < 8; m2++){
                float sa = sk, ca = ck;
                float sb = fmaf(sa, c1,  ca * s1);
                float cb = fmaf(ca, c1, -sa * s1);
                dst[m2] = make_float4(sa*d0, ca*d0, sb*d0, cb*d0);
                sk = fmaf(sb, c1,  cb * s1);
                ck = fmaf(cb, c1, -sb * s1);
            }
        } else if (wid < 4){
            // spline: thread = row; ratio chain — scaling f0 scales ALL values
            const int row = tid - 64;
            const float t  = sTime[p][row];
            const float d1 = sDispP[p][64 + row];
            float2* dst = sFeat + row * FSTRIDE + 16;
            const float a = (t + 2.0f) * 3.75f;
            int j0 = __float2int_rn(a);
            j0 = max(0, min(15, j0));
            const float d = a - (float)j0;
            const float f0 = __expf(-d * d) * d1;         // pre-scaled anchor
            dst[j0] = make_float2(f0, f0);
            float f = f0, r = __expf(fmaf(2.0f, d, -1.0f));
            #pragma unroll
            for (int k = 1; k <= 15; k++){
                f *= r; r *= E_M2;
                if (j0 + k <= 15) dst[j0 + k] = make_float2(f, f);
            }
            f = f0; r = __expf(fmaf(-2.0f, d, -1.0f));
            #pragma unroll
            for (int k = 1; k <= 15; k++){
                f *= r; r *= E_M2;
                if (j0 - k >= 0) dst[j0 - k] = make_float2(f, f);
            }
        } else if (wid < 6){
            // gauss: thread = (feature j, 16-row block); scale by d2
            const int tt = tid - 128;
            const int j  = tt & 15;
            const int r0 = (tt >> 4) << 4;
            #pragma unroll 4
            for (int k = 0; k < 16; k++){
                const int row = r0 + k;
                const float d2 = sDispP[p][128 + row];
                const float u = sTime[p][row] - bC;
                const float v = __expf(-u * u) * d2;
                sFeat[row * FSTRIDE + 32 + j] = make_float2(v, v);
            }
        } else {
            // wavelet: thread = (feature j, 8-row block), 4 warps; scale by d3
            const int tt = tid - 192;
            const int j  = tt & 15;
            const int r0 = (tt >> 4) << 3;
            #pragma unroll 4
            for (int k = 0; k < 8; k++){
                const int row = r0 + k;
                const float d3 = sDispP[p][192 + row];
                const float u  = (sTime[p][row] - bC) * bI;
                const float uu = u * u;
                const float v  = (1.0f - uu) * __expf(-0.5f * uu) * d3;
                sFeat[row * FSTRIDE + 48 + j] = make_float2(v, v);
            }
        }
        __syncthreads();   // sFeat ready

        // ===== phase 2: matvecs — no sel broadcast, no epilogue multiply ====
        const int rb = strm * 32;
        const float selv = sDispP[p][cat*64 + rb + lane];
        const unsigned act = __ballot_sync(0xffffffffu, selv != 0.f);
        ull* obase = (ull*)out + (size_t)(rowBase + rb) * 256 + dstA;

        if (job < 2){
            #pragma unroll 4
            for (int r = 0; r < 32; r++){
                ull* o = obase + (size_t)r * 256;
                if (act & (1u << r)){
                    const float2* feat = sFeat + (rb + r) * FSTRIDE;
                    ull a0 = 0, a1 = 0, a2 = 0, a3 = 0;
                    #pragma unroll
                    for (int i = 0; i < 8; i++){
                        ulonglong2 F = *(const ulonglong2*)(feat + 2*i);
                        a0 = fma2(wA[2*i],   F.x, a0);
                        a1 = fma2(wA[2*i+1], F.y, a1);
                        a2 = fma2(wB[2*i],   F.x, a2);
                        a3 = fma2(wB[2*i+1], F.y, a3);
                    }
                    float lA, hA, lB, hB;
                    unpack2(add2(a0, a1), lA, hA);
                    unpack2(add2(a2, a3), lB, hB);
                    *o = packf2(lA + hA, lB + hB);
                } else *o = 0ull;
            }
        } else {
            #pragma unroll 4
            for (int r = 0; r < 32; r++){
                ulonglong2* o = (ulonglong2*)(obase + (size_t)r * 256);
                ulonglong2 res;
                if (act & (1u << r)){
                    const float2* feat = sFeat + (rb + r) * FSTRIDE + foff;
                    ull a0 = 0, a1 = 0, a2 = 0, a3 = 0;
                    #pragma unroll
                    for (int i = 0; i < 8; i++){
                        ulonglong2 F = *(const ulonglong2*)(feat + 2*i);
                        a0 = fma2(wA[2*i],   F.x, a0);
                        a1 = fma2(wA[2*i+1], F.y, a1);
                        a2 = fma2(wB[2*i],   F.x, a2);
                        a3 = fma2(wB[2*i+1], F.y, a3);
                    }
                    res.x = add2(a0, a1);
                    res.y = add2(a2, a3);
                } else { res.x = 0ull; res.y = 0ull; }
                *o = res;
            }
        }

        p ^= 1;
    }
}

extern "C" void kernel_launch(void* const* d_in, const int* in_sizes, int n_in,
                              void* d_out, int out_size)
{
    const float* timestamp   = (const float*)d_in[0];
    const float* aux         = (const float*)d_in[1];
    const float* router_W    = (const float*)d_in[2];
    const float* router_b    = (const float*)d_in[3];
    const float* freqs       = (const float*)d_in[4];
    const float* fourier_W   = (const float*)d_in[5];
    const float* knots       = (const float*)d_in[6];
    const float* spline_W    = (const float*)d_in[7];
    const float* centers     = (const float*)d_in[8];
    const float* gauss_W     = (const float*)d_in[9];
    const float* wav_centers = (const float*)d_in[10];
    const float* wav_scales  = (const float*)d_in[11];
    const float* wavelet_W   = (const float*)d_in[12];
    float* out = (float*)d_out;

    const int B = in_sizes[0];

    mote_kernel<<<296, 320>>>(timestamp, aux, router_W, router_b, freqs,
                              fourier_W, knots, spline_W, centers, gauss_W,
                              wav_centers, wav_scales, wavelet_W, out, B);
}